// round 15
// baseline (speedup 1.0000x reference)
#include <cuda_runtime.h>
#include <cuda_bf16.h>
#include <math.h>

// ---------------- problem constants ----------------
#define Cc    256
#define HWp   16384      // 128*128
#define Ww    128
#define H1c   128
#define H2c   64
#define W2c   400
#define NPTS  (H1c*W2c)  // 51200
#define MQ    NPTS
#define MK    (H2c*W2c)  // 25600
#define DHc   32

// ---------------- scratch (device globals; no runtime alloc) ----------------
__device__ float  d_at[HWp*Cc];             // working image, HWC layout
__device__ __nv_bfloat16 d_aseqbf[MQ*Cc];
__device__ __nv_bfloat16 d_btbf[MK*Cc];     // list_b slice transposed to [M][K] bf16
__device__ __nv_bfloat16 d_qqbf[MQ*Cc];
__device__ __nv_bfloat16 d_kkbf[MK*Cc];
__device__ __nv_bfloat16 d_vvbf[MK*Cc];
__device__ __nv_bfloat16 d_obf[MQ*Cc];
__device__ float  d_rest[HWp*Cc];
__device__ float  d_rest2[HWp*Cc];
__device__ float  d_cnt[HWp];
__device__ float  d_cnt2[HWp];
__device__ int4   d_gidx[2*NPTS];
__device__ float2 d_wxy[2*NPTS];
__device__ int    d_sidx[2*NPTS];
__device__ float  d_bc[3*Cc];               // combined biases
__device__ __nv_bfloat16 d_WqT[Cc*Cc];      // combined Q weight bf16 K-major [k][n]
__device__ __nv_bfloat16 d_WkvT[Cc*2*Cc];   // stacked K|V weights bf16 K-major [k][512]
__device__ __nv_bfloat16 d_outwT[Cc*Cc];    // out_w bf16 K-major [k][n]
__device__ float  d_poskv[H2c*2*Cc];        // stacked pos bias [h][512] (K|V)

__device__ __forceinline__ unsigned sptr(const void* p) {
    return (unsigned)__cvta_generic_to_shared(p);
}
__device__ __forceinline__ unsigned bf2u(float a, float b) {
    __nv_bfloat162 t = __floats2bfloat162_rn(a, b);
    return *(unsigned*)&t;
}
// -------- vectorized global reduction (sm_90+) --------
__device__ __forceinline__ void red2(float* p, float a, float b) {
    asm volatile("red.global.add.v2.f32 [%0], {%1, %2};" :: "l"(p), "f"(a), "f"(b) : "memory");
}
// -------- cp.async --------
__device__ __forceinline__ void cp16(unsigned saddr, const void* g) {
    asm volatile("cp.async.ca.shared.global [%0], [%1], 16;" :: "r"(saddr), "l"(g));
}
#define CP_COMMIT() asm volatile("cp.async.commit_group;" ::: "memory")

#define LDMX4(r0,r1,r2,r3,addr) \
    asm volatile("ldmatrix.sync.aligned.m8n8.x4.shared.b16 {%0,%1,%2,%3},[%4];" \
        : "=r"(r0),"=r"(r1),"=r"(r2),"=r"(r3) : "r"(addr))
#define LDMX4T(r0,r1,r2,r3,addr) \
    asm volatile("ldmatrix.sync.aligned.m8n8.x4.trans.shared.b16 {%0,%1,%2,%3},[%4];" \
        : "=r"(r0),"=r"(r1),"=r"(r2),"=r"(r3) : "r"(addr))
#define MMABF16(c0,c1,c2,c3,a0,a1,a2,a3,b0,b1) \
    asm volatile("mma.sync.aligned.m16n8k16.row.col.f32.bf16.bf16.f32 " \
        "{%0,%1,%2,%3},{%4,%5,%6,%7},{%8,%9},{%0,%1,%2,%3};" \
        : "+f"(c0),"+f"(c1),"+f"(c2),"+f"(c3) \
        : "r"(a0),"r"(a1),"r"(a2),"r"(a3),"r"(b0),"r"(b1))

// ---------------- zero rest/rest2/cnt/cnt2 ----------------
__global__ void k_zero() {
    size_t i = (size_t)blockIdx.x * 256 + threadIdx.x;
    float4 z = make_float4(0.f, 0.f, 0.f, 0.f);
    ((float4*)d_rest)[i]  = z;      // grid covers HWp*Cc/4 exactly
    ((float4*)d_rest2)[i] = z;
    if (i < HWp / 4) { ((float4*)d_cnt)[i] = z; ((float4*)d_cnt2)[i] = z; }
}

// ---------------- coords for BOTH passes (+ scatter counts) ----------------
__global__ void k_coords_all(const float* __restrict__ rots, const float* __restrict__ fxs,
                             const float* __restrict__ cxs) {
    int p = blockIdx.x * blockDim.x + threadIdx.x;
    int ji = blockIdx.y;
    if (p >= NPTS) return;
    int j = ji * 3;  // cams 0 and 3
    int r = p / W2c, w = p % W2c;
    float fx = fxs[j], cx = cxs[j];
    float cth = rots[j * 9 + 0];
    float sth = rots[j * 9 + 3];
    float ang = atanf((w * 2.0f + 1.0f - cx) / fx);
    float cA = cosf(ang), sA = sinf(ang);
    float ca = sth * cA - cth * sA;
    float sa = cth * cA + sth * sA;
    float rmax = sqrtf(64.f * 64.f + 64.f * 64.f);
    float rad = ((float)r / 127.0f) * rmax;
    float x = 64.f + rad * ca;
    float y = 64.f - rad * sa;
    float xc = fminf(fmaxf(x, 0.f), 127.f);
    float yc = fminf(fmaxf(y, 0.f), 127.f);
    float x0 = floorf(xc), y0 = floorf(yc);
    float x1 = fminf(x0 + 1.f, 127.f), y1 = fminf(y0 + 1.f, 127.f);
    int x0i = (int)x0, x1i = (int)x1, y0i = (int)y0, y1i = (int)y1;
    int q = ji * NPTS + p;
    d_gidx[q] = make_int4(y0i * Ww + x0i, y0i * Ww + x1i, y1i * Ww + x0i, y1i * Ww + x1i);
    d_wxy[q]  = make_float2(xc - x0, yc - y0);
    int xi = (int)fminf(fmaxf(rintf(x), 0.f), 127.f);
    int yi = (int)fminf(fmaxf(rintf(y), 0.f), 127.f);
    int si = yi * Ww + xi;
    d_sidx[q] = si;
    atomicAdd((ji == 0 ? d_cnt : d_cnt2) + si, 1.0f);
}

// ---------------- combined weights + bias + bf16 K-major transposes ----------------
__global__ void k_combine_all(const float* __restrict__ Wq, const float* __restrict__ Wk,
                              const float* __restrict__ Wv, const float* __restrict__ in_w,
                              const float* __restrict__ bq, const float* __restrict__ bk,
                              const float* __restrict__ bv, const float* __restrict__ in_b,
                              const float* __restrict__ out_w) {
    int n = blockIdx.x, sel = blockIdx.y, c = threadIdx.x;
    if (sel == 3) {
        d_outwT[(size_t)c * Cc + n] = __float2bfloat16_rn(out_w[(size_t)n * Cc + c]);
        return;
    }
    const float* W = (sel == 0) ? Wq : ((sel == 1) ? Wk : Wv);
    const float* b = (sel == 0) ? bq : ((sel == 1) ? bk : bv);
    __shared__ float ir[Cc];
    __shared__ float red[8];
    ir[c] = in_w[(size_t)(sel * Cc + n) * Cc + c];
    __syncthreads();
    float s = 0.f;
    #pragma unroll 8
    for (int m = 0; m < Cc; m++) s += ir[m] * W[(size_t)m * Cc + c];
    if (sel == 0) d_WqT[(size_t)c * Cc + n] = __float2bfloat16_rn(s);
    else d_WkvT[(size_t)c * 512 + (sel - 1) * Cc + n] = __float2bfloat16_rn(s);
    float pb = ir[c] * b[c];
    #pragma unroll
    for (int o = 16; o > 0; o >>= 1) pb += __shfl_down_sync(0xffffffffu, pb, o);
    if ((c & 31) == 0) red[c >> 5] = pb;
    __syncthreads();
    if (c == 0) {
        float t = 0.f;
        #pragma unroll
        for (int i = 0; i < 8; i++) t += red[i];
        d_bc[sel * Cc + n] = t + in_b[sel * Cc + n];
    }
}

// poskv[h][which*256+n] = sum_c pos_b[h][c]*WkvT[c][which*256+n] + bc[(which+1)*256+n]
__global__ void k_pos_proj(const float* __restrict__ pos_b) {
    int h = blockIdx.x, which = blockIdx.y, n = threadIdx.x;
    __shared__ float pb[Cc];
    pb[n] = pos_b[(size_t)h * Cc + n];
    __syncthreads();
    float s = d_bc[(which + 1) * Cc + n];
    #pragma unroll 8
    for (int c = 0; c < Cc; c++)
        s += pb[c] * __bfloat162float(d_WkvT[(size_t)c * 512 + which * 256 + n]);
    d_poskv[(size_t)h * 512 + which * 256 + n] = s;
}

// ---------------- transpose+convert list_b slice [C][M] fp32 -> [M][C] bf16 ----------
__global__ void k_b2bt(const float* __restrict__ src) {
    __shared__ float tile[32][33];
    int m0 = blockIdx.x * 32, c0 = blockIdx.y * 32;
    int tx = threadIdx.x;
    for (int i = threadIdx.y; i < 32; i += 8)
        tile[i][tx] = src[(size_t)(c0 + i) * MK + m0 + tx];
    __syncthreads();
    for (int i = threadIdx.y; i < 32; i += 8)
        d_btbf[(size_t)(m0 + i) * Cc + c0 + tx] = __float2bfloat16_rn(tile[tx][i]);
}

// ---------------- input transpose: (C,H,W) -> (HW, C) ----------------
__global__ void k_transpose_in(const float* __restrict__ a) {
    __shared__ float tile[32][33];
    int hw0 = blockIdx.x * 32;
    int c0  = blockIdx.y * 32;
    for (int i = threadIdx.y; i < 32; i += 8)
        tile[i][threadIdx.x] = a[(size_t)(c0 + i) * HWp + hw0 + threadIdx.x];
    __syncthreads();
    for (int i = threadIdx.y; i < 32; i += 8)
        d_at[(size_t)(hw0 + i) * Cc + c0 + threadIdx.x] = tile[threadIdx.x][i];
}

// ---------------- a_seq = bilinear(a_t) + pos_a  ->  bf16 ----------------
__global__ __launch_bounds__(256) void k_build_aseq(const float* __restrict__ pos_a, int ji) {
    int tx = threadIdx.x & 63;
    int ty = threadIdx.x >> 6;
    int p  = blockIdx.x * 4 + ty;
    int r = p / W2c, w = p % W2c;
    int q = ji * NPTS + p;
    int4 g = d_gidx[q];
    float2 wt = d_wxy[q];
    float w11 = wt.x * wt.y;
    float w01 = wt.x - w11;
    float w10 = wt.y - w11;
    float w00 = 1.f - wt.x - wt.y + w11;
    float4 v00 = ((const float4*)(d_at + (size_t)g.x * Cc))[tx];
    float4 v01 = ((const float4*)(d_at + (size_t)g.y * Cc))[tx];
    float4 v10 = ((const float4*)(d_at + (size_t)g.z * Cc))[tx];
    float4 v11 = ((const float4*)(d_at + (size_t)g.w * Cc))[tx];
    float4 pa  = ((const float4*)(pos_a + (size_t)r * Cc))[tx];
    float o0 = v00.x * w00 + v01.x * w01 + v10.x * w10 + v11.x * w11 + pa.x;
    float o1 = v00.y * w00 + v01.y * w01 + v10.y * w10 + v11.y * w11 + pa.y;
    float o2 = v00.z * w00 + v01.z * w01 + v10.z * w10 + v11.z * w11 + pa.z;
    float o3 = v00.w * w00 + v01.w * w01 + v10.w * w10 + v11.w * w11 + pa.w;
    int row = w * H1c + r;
    uint2 u = {bf2u(o0, o1), bf2u(o2, o3)};
    *(uint2*)(d_aseqbf + (size_t)row * Cc + tx * 4) = u;
}

// ================= cp.async pipelined bf16 mma GEMM — 128x64 tile, 3 CTAs/SM ==========
// Tile: M=128, N=64. Warps 4m x 2n; per-warp 32x32; 32 accums/thread.
#define GSM_A(st)  ((st) * 10240)               // A stage: 128 x 40 bf16 = 10240 B
#define GSM_B(st)  (30720 + (st) * 4608)        // B stage: 32 x 72 bf16 = 4608 B
#define GSM_TOTAL  44544
template<int OUTMODE, int BIASMODE>
__global__ __launch_bounds__(256) void k_mma_gemm(const __nv_bfloat16* __restrict__ A,
                                                  const __nv_bfloat16* __restrict__ BT,
                                                  const float* __restrict__ bias,
                                                  __nv_bfloat16* __restrict__ outA,
                                                  __nv_bfloat16* __restrict__ outB,
                                                  float* __restrict__ restP,
                                                  int ldb, int biasld, int sidx_off) {
    extern __shared__ __align__(16) char gsm[];
    unsigned sbase = sptr(gsm);
    int t = threadIdx.x, lane = t & 31, warp = t >> 5;
    int m0 = blockIdx.x * 128, n0 = blockIdx.y * 64;
    int wm = (warp & 3) * 32;
    int wn = (warp >> 2) * 32;

    int am0 = t >> 2,            akq0 = (t & 3) * 8;
    int am1 = (t + 256) >> 2,    akq1 = (t & 3) * 8;
    int bk0 = t >> 3,            bn0 = (t & 7) * 8;     // 32 k-rows x 64 n-cols, 1 cp16/thread

    #define GISSUE(st, k0) do { \
        unsigned ab = sbase + GSM_A(st); \
        unsigned bb = sbase + GSM_B(st); \
        cp16(ab + (am0 * 40 + akq0) * 2, A + (size_t)(m0 + am0) * Cc + (k0) + akq0); \
        cp16(ab + (am1 * 40 + akq1) * 2, A + (size_t)(m0 + am1) * Cc + (k0) + akq1); \
        cp16(bb + (bk0 * 72 + bn0) * 2, BT + (size_t)((k0) + bk0) * ldb + n0 + bn0); \
    } while (0)

    float acc[2][4][4];
    #pragma unroll
    for (int i = 0; i < 2; i++)
        #pragma unroll
        for (int j = 0; j < 4; j++)
            #pragma unroll
            for (int q = 0; q < 4; q++) acc[i][j][q] = 0.f;

    GISSUE(0, 0);  CP_COMMIT();
    GISSUE(1, 32); CP_COMMIT();

    #pragma unroll 1
    for (int iter = 0; iter < 8; iter++) {
        if (iter < 7) asm volatile("cp.async.wait_group 1;" ::: "memory");
        else          asm volatile("cp.async.wait_group 0;" ::: "memory");
        __syncthreads();
        if (iter < 6) {
            int st = iter + 2;
            int buf = st - (st >= 6 ? 6 : (st >= 3 ? 3 : 0));
            GISSUE(buf, st * 32);
            CP_COMMIT();
        }
        int s = iter - (iter >= 6 ? 6 : (iter >= 3 ? 3 : 0));
        unsigned ab = sbase + GSM_A(s);
        unsigned bb = sbase + GSM_B(s);
        #pragma unroll
        for (int kk = 0; kk < 32; kk += 16) {
            unsigned a[2][4], b[4][2];
            #pragma unroll
            for (int i = 0; i < 2; i++) {
                unsigned addr = ab + ((wm + i * 16 + (lane & 15)) * 40 + kk + (lane >> 4) * 8) * 2;
                LDMX4(a[i][0], a[i][1], a[i][2], a[i][3], addr);
            }
            #pragma unroll
            for (int jn = 0; jn < 2; jn++) {
                unsigned addr = bb + ((kk + (lane & 15)) * 72 + wn + jn * 16 + (lane >> 4) * 8) * 2;
                unsigned r0, r1, r2, r3;
                LDMX4T(r0, r1, r2, r3, addr);
                b[2 * jn][0] = r0; b[2 * jn][1] = r1;
                b[2 * jn + 1][0] = r2; b[2 * jn + 1][1] = r3;
            }
            #pragma unroll
            for (int i = 0; i < 2; i++)
                #pragma unroll
                for (int j = 0; j < 4; j++)
                    MMABF16(acc[i][j][0], acc[i][j][1], acc[i][j][2], acc[i][j][3],
                            a[i][0], a[i][1], a[i][2], a[i][3], b[j][0], b[j][1]);
        }
    }
    #undef GISSUE

    #pragma unroll
    for (int i = 0; i < 2; i++) {
        int mrow = m0 + wm + i * 16 + (lane >> 2);
        #pragma unroll
        for (int j = 0; j < 4; j++) {
            int n = n0 + wn + j * 8 + (lane & 3) * 2;
            float b0, b1, b2, b3;
            if (BIASMODE == 0) {
                b0 = bias[n]; b1 = bias[n + 1]; b2 = b0; b3 = b1;
            } else {
                int h0 = mrow / 400, h1 = (mrow + 8) / 400;
                b0 = bias[(size_t)h0 * biasld + n]; b1 = bias[(size_t)h0 * biasld + n + 1];
                b2 = bias[(size_t)h1 * biasld + n]; b3 = bias[(size_t)h1 * biasld + n + 1];
            }
            float v00 = acc[i][j][0] + b0, v01 = acc[i][j][1] + b1;
            float v10 = acc[i][j][2] + b2, v11 = acc[i][j][3] + b3;
            if (OUTMODE == 1) {
                __nv_bfloat16* o = (n < 256) ? outA : outB;
                int col = n & 255;
                *(__nv_bfloat162*)(o + (size_t)mrow * Cc + col) = __floats2bfloat162_rn(v00, v01);
                *(__nv_bfloat162*)(o + (size_t)(mrow + 8) * Cc + col) = __floats2bfloat162_rn(v10, v11);
            } else {
                int p0 = (mrow & 127) * W2c + (mrow >> 7);
                int p1 = ((mrow + 8) & 127) * W2c + ((mrow + 8) >> 7);
                int s0 = d_sidx[sidx_off + p0];
                int s1 = d_sidx[sidx_off + p1];
                red2(&restP[(size_t)s0 * Cc + n], v00, v01);
                red2(&restP[(size_t)s1 * Cc + n], v10, v11);
            }
        }
    }
}

// ---------------- tensor-core flash attention: grid (w=400, h=8), 128 threads ----------
__global__ __launch_bounds__(128) void k_attn_tc() {
    int w = blockIdx.x, h = blockIdx.y;
    int t = threadIdx.x, lane = t & 31, warp = t >> 5;
    __shared__ __align__(16) __nv_bfloat16 Qs[128 * 40];
    __shared__ __align__(16) __nv_bfloat16 Ks[64 * 40];
    __shared__ __align__(16) __nv_bfloat16 Vs[64 * 40];

    #pragma unroll
    for (int i = 0; i < 4; i++) {
        int slot = i * 128 + t;
        int row = slot >> 2, q4 = slot & 3;
        uint4 v = *(const uint4*)(d_qqbf + (size_t)(w * H1c + row) * Cc + h * DHc + q4 * 8);
        *(uint4*)(Qs + row * 40 + q4 * 8) = v;
    }
    #pragma unroll
    for (int i = 0; i < 2; i++) {
        int slot = i * 128 + t;
        int key = slot >> 2, q4 = slot & 3;
        size_t src = (size_t)(key * W2c + w) * Cc + h * DHc + q4 * 8;
        *(uint4*)(Ks + key * 40 + q4 * 8) = *(const uint4*)(d_kkbf + src);
        *(uint4*)(Vs + key * 40 + q4 * 8) = *(const uint4*)(d_vvbf + src);
    }
    __syncthreads();

    int wm = warp * 32;
    unsigned qa[2][2][4];
    #pragma unroll
    for (int i = 0; i < 2; i++)
        #pragma unroll
        for (int ks = 0; ks < 2; ks++) {
            unsigned addr = sptr(Qs + (wm + i * 16 + (lane & 15)) * 40 + ks * 16 + (lane >> 4) * 8);
            LDMX4(qa[i][ks][0], qa[i][ks][1], qa[i][ks][2], qa[i][ks][3], addr);
        }

    float sacc[2][8][4];
    #pragma unroll
    for (int i = 0; i < 2; i++)
        #pragma unroll
        for (int j = 0; j < 8; j++)
            #pragma unroll
            for (int q = 0; q < 4; q++) sacc[i][j][q] = 0.f;

    #pragma unroll
    for (int ks = 0; ks < 2; ks++) {
        #pragma unroll
        for (int ng = 0; ng < 4; ng++) {
            int row = ng * 16 + ((lane >> 4) & 1) * 8 + (lane & 7);
            int col = ((lane >> 3) & 1) * 8 + ks * 16;
            unsigned r0, r1, r2, r3;
            LDMX4(r0, r1, r2, r3, sptr(Ks + row * 40 + col));
            #pragma unroll
            for (int i = 0; i < 2; i++) {
                MMABF16(sacc[i][2 * ng][0], sacc[i][2 * ng][1], sacc[i][2 * ng][2], sacc[i][2 * ng][3],
                        qa[i][ks][0], qa[i][ks][1], qa[i][ks][2], qa[i][ks][3], r0, r1);
                MMABF16(sacc[i][2 * ng + 1][0], sacc[i][2 * ng + 1][1], sacc[i][2 * ng + 1][2], sacc[i][2 * ng + 1][3],
                        qa[i][ks][0], qa[i][ks][1], qa[i][ks][2], qa[i][ks][3], r2, r3);
            }
        }
    }

    const float sc = 0.17677669529663687f;  // 1/sqrt(32)
    float mx[2][2], ls[2][2];
    #pragma unroll
    for (int i = 0; i < 2; i++) {
        mx[i][0] = -INFINITY; mx[i][1] = -INFINITY;
        #pragma unroll
        for (int j = 0; j < 8; j++) {
            mx[i][0] = fmaxf(mx[i][0], fmaxf(sacc[i][j][0], sacc[i][j][1]));
            mx[i][1] = fmaxf(mx[i][1], fmaxf(sacc[i][j][2], sacc[i][j][3]));
        }
    }
    #pragma unroll
    for (int i = 0; i < 2; i++)
        #pragma unroll
        for (int s = 0; s < 2; s++) {
            float v = mx[i][s];
            v = fmaxf(v, __shfl_xor_sync(0xffffffffu, v, 1));
            v = fmaxf(v, __shfl_xor_sync(0xffffffffu, v, 2));
            mx[i][s] = v;
        }
    #pragma unroll
    for (int i = 0; i < 2; i++) {
        ls[i][0] = 0.f; ls[i][1] = 0.f;
        #pragma unroll
        for (int j = 0; j < 8; j++) {
            sacc[i][j][0] = __expf((sacc[i][j][0] - mx[i][0]) * sc);
            sacc[i][j][1] = __expf((sacc[i][j][1] - mx[i][0]) * sc);
            sacc[i][j][2] = __expf((sacc[i][j][2] - mx[i][1]) * sc);
            sacc[i][j][3] = __expf((sacc[i][j][3] - mx[i][1]) * sc);
            ls[i][0] += sacc[i][j][0] + sacc[i][j][1];
            ls[i][1] += sacc[i][j][2] + sacc[i][j][3];
        }
    }
    #pragma unroll
    for (int i = 0; i < 2; i++)
        #pragma unroll
        for (int s = 0; s < 2; s++) {
            float v = ls[i][s];
            v += __shfl_xor_sync(0xffffffffu, v, 1);
            v += __shfl_xor_sync(0xffffffffu, v, 2);
            ls[i][s] = v;
        }

    unsigned pa[2][4][4];
    #pragma unroll
    for (int i = 0; i < 2; i++)
        #pragma unroll
        for (int s = 0; s < 4; s++) {
            pa[i][s][0] = bf2u(sacc[i][2 * s][0],     sacc[i][2 * s][1]);
            pa[i][s][1] = bf2u(sacc[i][2 * s][2],     sacc[i][2 * s][3]);
            pa[i][s][2] = bf2u(sacc[i][2 * s + 1][0], sacc[i][2 * s + 1][1]);
            pa[i][s][3] = bf2u(sacc[i][2 * s + 1][2], sacc[i][2 * s + 1][3]);
        }

    float oacc[2][4][4];
    #pragma unroll
    for (int i = 0; i < 2; i++)
        #pragma unroll
        for (int j = 0; j < 4; j++)
            #pragma unroll
            for (int q = 0; q < 4; q++) oacc[i][j][q] = 0.f;
    #pragma unroll
    for (int s = 0; s < 4; s++) {
        #pragma unroll
        for (int jn = 0; jn < 2; jn++) {
            unsigned r0, r1, r2, r3;
            LDMX4T(r0, r1, r2, r3,
                   sptr(Vs + (s * 16 + (lane & 15)) * 40 + jn * 16 + (lane >> 4) * 8));
            #pragma unroll
            for (int i = 0; i < 2; i++) {
                MMABF16(oacc[i][2 * jn][0], oacc[i][2 * jn][1], oacc[i][2 * jn][2], oacc[i][2 * jn][3],
                        pa[i][s][0], pa[i][s][1], pa[i][s][2], pa[i][s][3], r0, r1);
                MMABF16(oacc[i][2 * jn + 1][0], oacc[i][2 * jn + 1][1], oacc[i][2 * jn + 1][2], oacc[i][2 * jn + 1][3],
                        pa[i][s][0], pa[i][s][1], pa[i][s][2], pa[i][s][3], r2, r3);
            }
        }
    }

    #pragma unroll
    for (int i = 0; i < 2; i++) {
        float inv0 = 1.f / ls[i][0], inv1 = 1.f / ls[i][1];
        int r0w = w * H1c + wm + i * 16 + (lane >> 2);
        #pragma unroll
        for (int j = 0; j < 4; j++) {
            int col = h * DHc + j * 8 + (lane & 3) * 2;
            *(__nv_bfloat162*)(d_obf + (size_t)r0w * Cc + col) =
                __floats2bfloat162_rn(oacc[i][j][0] * inv0, oacc[i][j][1] * inv0);
            *(__nv_bfloat162*)(d_obf + (size_t)(r0w + 8) * Cc + col) =
                __floats2bfloat162_rn(oacc[i][j][2] * inv1, oacc[i][j][3] * inv1);
        }
    }
}

// ---------------- update (pass 1): at += rest/cnt ----------------
__global__ void k_update() {
    int hw = blockIdx.x, c = threadIdx.x;
    float cnt = d_cnt[hw];
    cnt = (cnt == 0.f) ? 1.f : cnt;
    size_t idx = (size_t)hw * Cc + c;
    d_at[idx] += d_rest[idx] / cnt;
}

// ---------------- final: out[c][hw] = at[hw][c] + 2*rest2[hw][c]/cnt2[hw] ----------------
__global__ void k_writeout(float* __restrict__ out) {
    __shared__ float tile[32][33];
    int hw0 = blockIdx.x * 32;
    int c0  = blockIdx.y * 32;
    int tx = threadIdx.x;
    for (int i = threadIdx.y; i < 32; i += 8) {
        float cnt = d_cnt2[hw0 + i];
        cnt = (cnt == 0.f) ? 1.f : cnt;
        size_t idx = (size_t)(hw0 + i) * Cc + c0 + tx;
        tile[i][tx] = d_at[idx] + 2.f * d_rest2[idx] / cnt;
    }
    __syncthreads();
    for (int i = threadIdx.y; i < 32; i += 8)
        out[(size_t)(c0 + i) * HWp + hw0 + tx] = tile[tx][i];
}

// ---------------- host launcher (single stream) ----------------
extern "C" void kernel_launch(void* const* d_in, const int* in_sizes, int n_in,
                              void* d_out, int out_size) {
    const float* list_a = (const float*)d_in[0];
    const float* list_b = (const float*)d_in[1];
    const float* rots   = (const float*)d_in[3];
    const float* fxs    = (const float*)d_in[5];
    const float* cxs    = (const float*)d_in[6];
    const float* pos_a  = (const float*)d_in[7];
    const float* pos_b  = (const float*)d_in[8];
    const float* Wq     = (const float*)d_in[9];
    const float* bq     = (const float*)d_in[10];
    const float* Wk     = (const float*)d_in[11];
    const float* bk     = (const float*)d_in[12];
    const float* Wv     = (const float*)d_in[13];
    const float* bv     = (const float*)d_in[14];
    const float* in_w   = (const float*)d_in[15];
    const float* in_b   = (const float*)d_in[16];
    const float* out_w  = (const float*)d_in[17];
    const float* out_b  = (const float*)d_in[18];
    float* out = (float*)d_out;

    float *p_bc, *p_poskv, *p_rest, *p_rest2;
    __nv_bfloat16 *p_aseqbf, *p_btbf, *p_qqbf, *p_kkbf, *p_vvbf, *p_obf,
                  *p_WqT, *p_WkvT, *p_outwT;
    cudaGetSymbolAddress((void**)&p_bc,     d_bc);
    cudaGetSymbolAddress((void**)&p_poskv,  d_poskv);
    cudaGetSymbolAddress((void**)&p_rest,   d_rest);
    cudaGetSymbolAddress((void**)&p_rest2,  d_rest2);
    cudaGetSymbolAddress((void**)&p_aseqbf, d_aseqbf);
    cudaGetSymbolAddress((void**)&p_btbf,   d_btbf);
    cudaGetSymbolAddress((void**)&p_qqbf,   d_qqbf);
    cudaGetSymbolAddress((void**)&p_kkbf,   d_kkbf);
    cudaGetSymbolAddress((void**)&p_vvbf,   d_vvbf);
    cudaGetSymbolAddress((void**)&p_obf,    d_obf);
    cudaGetSymbolAddress((void**)&p_WqT,    d_WqT);
    cudaGetSymbolAddress((void**)&p_WkvT,   d_WkvT);
    cudaGetSymbolAddress((void**)&p_outwT,  d_outwT);

    cudaFuncSetAttribute(k_mma_gemm<1, 0>, cudaFuncAttributeMaxDynamicSharedMemorySize, GSM_TOTAL);
    cudaFuncSetAttribute(k_mma_gemm<1, 1>, cudaFuncAttributeMaxDynamicSharedMemorySize, GSM_TOTAL);
    cudaFuncSetAttribute(k_mma_gemm<2, 0>, cudaFuncAttributeMaxDynamicSharedMemorySize, GSM_TOTAL);

    k_zero<<<4096, 256>>>();                                                         // 0
    k_coords_all<<<dim3((NPTS + 255) / 256, 2), 256>>>(rots, fxs, cxs);              // 1
    k_combine_all<<<dim3(Cc, 4), Cc>>>(Wq, Wk, Wv, in_w, bq, bk, bv, in_b, out_w);   // 2
    k_pos_proj<<<dim3(H2c, 2), Cc>>>(pos_b);                                         // 3
    k_b2bt<<<dim3(MK / 32, Cc / 32), dim3(32, 8)>>>(list_b);                         // 4
    k_mma_gemm<1, 1><<<dim3(MK / 128, 8), 256, GSM_TOTAL>>>(                         // 5 <- profiled
        p_btbf, p_WkvT, p_poskv, p_kkbf, p_vvbf, nullptr, 512, 512, 0);
    k_transpose_in<<<dim3(HWp / 32, Cc / 32), dim3(32, 8)>>>(list_a);                // 6

    for (int ji = 0; ji < 2; ji++) {
        if (ji == 1) {
            k_b2bt<<<dim3(MK / 32, Cc / 32), dim3(32, 8)>>>(list_b + (size_t)3 * Cc * MK);
            k_mma_gemm<1, 1><<<dim3(MK / 128, 8), 256, GSM_TOTAL>>>(
                p_btbf, p_WkvT, p_poskv, p_kkbf, p_vvbf, nullptr, 512, 512, 0);
        }
        k_build_aseq<<<NPTS / 4, 256>>>(pos_a, ji);
        k_mma_gemm<1, 0><<<dim3(MQ / 128, 4), 256, GSM_TOTAL>>>(
            p_aseqbf, p_WqT, p_bc, p_qqbf, p_qqbf, nullptr, 256, 0, 0);
        k_attn_tc<<<dim3(W2c, 8), 128>>>();
        k_mma_gemm<2, 0><<<dim3(MQ / 128, 4), 256, GSM_TOTAL>>>(
            p_obf, p_outwT, out_b, nullptr, nullptr, ji == 0 ? p_rest : p_rest2,
            256, 0, ji * NPTS);
        if (ji == 0) k_update<<<HWp, Cc>>>();
    }
    k_writeout<<<dim3(HWp / 32, Cc / 32), dim3(32, 8)>>>(out);
}

// round 16
// speedup vs baseline: 1.0300x; 1.0300x over previous
#include <cuda_runtime.h>
#include <cuda_bf16.h>
#include <math.h>

// ---------------- problem constants ----------------
#define Cc    256
#define HWp   16384      // 128*128
#define Ww    128
#define H1c   128
#define H2c   64
#define W2c   400
#define NPTS  (H1c*W2c)  // 51200
#define MQ    NPTS
#define MK    (H2c*W2c)  // 25600
#define DHc   32

// ---------------- scratch (device globals; no runtime alloc) ----------------
__device__ float  d_at[HWp*Cc];             // working image, HWC layout
__device__ __nv_bfloat16 d_aseqbf[MQ*Cc];
__device__ __nv_bfloat16 d_btbf[MK*Cc];     // list_b slice transposed to [M][K] bf16
__device__ __nv_bfloat16 d_qqbf[MQ*Cc];
__device__ __nv_bfloat16 d_kkbf[MK*Cc];
__device__ __nv_bfloat16 d_vvbf[MK*Cc];
__device__ __nv_bfloat16 d_obf[MQ*Cc];
__device__ float  d_rest[HWp*Cc];
__device__ float  d_rest2[HWp*Cc];
__device__ float  d_cnt[HWp];
__device__ float  d_cnt2[HWp];
__device__ int4   d_gidx[2*NPTS];
__device__ float2 d_wxy[2*NPTS];
__device__ int    d_sidx[2*NPTS];
__device__ float  d_bc[3*Cc];               // combined biases
__device__ __nv_bfloat16 d_WqT[Cc*Cc];      // combined Q weight bf16 K-major [k][n]
__device__ __nv_bfloat16 d_WkvT[Cc*2*Cc];   // stacked K|V weights bf16 K-major [k][512]
__device__ __nv_bfloat16 d_outwT[Cc*Cc];    // out_w bf16 K-major [k][n]
__device__ float  d_poskv[H2c*2*Cc];        // stacked pos bias [h][512] (K|V)

__device__ __forceinline__ unsigned sptr(const void* p) {
    return (unsigned)__cvta_generic_to_shared(p);
}
__device__ __forceinline__ unsigned bf2u(float a, float b) {
    __nv_bfloat162 t = __floats2bfloat162_rn(a, b);
    return *(unsigned*)&t;
}
// -------- vectorized global reduction (sm_90+) --------
__device__ __forceinline__ void red2(float* p, float a, float b) {
    asm volatile("red.global.add.v2.f32 [%0], {%1, %2};" :: "l"(p), "f"(a), "f"(b) : "memory");
}
// -------- cp.async --------
__device__ __forceinline__ void cp16(unsigned saddr, const void* g) {
    asm volatile("cp.async.ca.shared.global [%0], [%1], 16;" :: "r"(saddr), "l"(g));
}
#define CP_COMMIT() asm volatile("cp.async.commit_group;" ::: "memory")

#define LDMX4(r0,r1,r2,r3,addr) \
    asm volatile("ldmatrix.sync.aligned.m8n8.x4.shared.b16 {%0,%1,%2,%3},[%4];" \
        : "=r"(r0),"=r"(r1),"=r"(r2),"=r"(r3) : "r"(addr))
#define LDMX4T(r0,r1,r2,r3,addr) \
    asm volatile("ldmatrix.sync.aligned.m8n8.x4.trans.shared.b16 {%0,%1,%2,%3},[%4];" \
        : "=r"(r0),"=r"(r1),"=r"(r2),"=r"(r3) : "r"(addr))
#define MMABF16(c0,c1,c2,c3,a0,a1,a2,a3,b0,b1) \
    asm volatile("mma.sync.aligned.m16n8k16.row.col.f32.bf16.bf16.f32 " \
        "{%0,%1,%2,%3},{%4,%5,%6,%7},{%8,%9},{%0,%1,%2,%3};" \
        : "+f"(c0),"+f"(c1),"+f"(c2),"+f"(c3) \
        : "r"(a0),"r"(a1),"r"(a2),"r"(a3),"r"(b0),"r"(b1))

// ---------------- zero rest/rest2/cnt/cnt2 ----------------
__global__ void k_zero() {
    size_t i = (size_t)blockIdx.x * 256 + threadIdx.x;
    float4 z = make_float4(0.f, 0.f, 0.f, 0.f);
    ((float4*)d_rest)[i]  = z;      // grid covers HWp*Cc/4 exactly
    ((float4*)d_rest2)[i] = z;
    if (i < HWp / 4) { ((float4*)d_cnt)[i] = z; ((float4*)d_cnt2)[i] = z; }
}

// ---------------- coords for BOTH passes (+ scatter counts) ----------------
__global__ void k_coords_all(const float* __restrict__ rots, const float* __restrict__ fxs,
                             const float* __restrict__ cxs) {
    int p = blockIdx.x * blockDim.x + threadIdx.x;
    int ji = blockIdx.y;
    if (p >= NPTS) return;
    int j = ji * 3;  // cams 0 and 3
    int r = p / W2c, w = p % W2c;
    float fx = fxs[j], cx = cxs[j];
    float cth = rots[j * 9 + 0];
    float sth = rots[j * 9 + 3];
    float ang = atanf((w * 2.0f + 1.0f - cx) / fx);
    float cA = cosf(ang), sA = sinf(ang);
    float ca = sth * cA - cth * sA;
    float sa = cth * cA + sth * sA;
    float rmax = sqrtf(64.f * 64.f + 64.f * 64.f);
    float rad = ((float)r / 127.0f) * rmax;
    float x = 64.f + rad * ca;
    float y = 64.f - rad * sa;
    float xc = fminf(fmaxf(x, 0.f), 127.f);
    float yc = fminf(fmaxf(y, 0.f), 127.f);
    float x0 = floorf(xc), y0 = floorf(yc);
    float x1 = fminf(x0 + 1.f, 127.f), y1 = fminf(y0 + 1.f, 127.f);
    int x0i = (int)x0, x1i = (int)x1, y0i = (int)y0, y1i = (int)y1;
    int q = ji * NPTS + p;
    d_gidx[q] = make_int4(y0i * Ww + x0i, y0i * Ww + x1i, y1i * Ww + x0i, y1i * Ww + x1i);
    d_wxy[q]  = make_float2(xc - x0, yc - y0);
    int xi = (int)fminf(fmaxf(rintf(x), 0.f), 127.f);
    int yi = (int)fminf(fmaxf(rintf(y), 0.f), 127.f);
    int si = yi * Ww + xi;
    d_sidx[q] = si;
    atomicAdd((ji == 0 ? d_cnt : d_cnt2) + si, 1.0f);
}

// ---------------- combined weights + bias + bf16 K-major transposes ----------------
__global__ void k_combine_all(const float* __restrict__ Wq, const float* __restrict__ Wk,
                              const float* __restrict__ Wv, const float* __restrict__ in_w,
                              const float* __restrict__ bq, const float* __restrict__ bk,
                              const float* __restrict__ bv, const float* __restrict__ in_b,
                              const float* __restrict__ out_w) {
    int n = blockIdx.x, sel = blockIdx.y, c = threadIdx.x;
    if (sel == 3) {
        d_outwT[(size_t)c * Cc + n] = __float2bfloat16_rn(out_w[(size_t)n * Cc + c]);
        return;
    }
    const float* W = (sel == 0) ? Wq : ((sel == 1) ? Wk : Wv);
    const float* b = (sel == 0) ? bq : ((sel == 1) ? bk : bv);
    __shared__ float ir[Cc];
    __shared__ float red[8];
    ir[c] = in_w[(size_t)(sel * Cc + n) * Cc + c];
    __syncthreads();
    float s = 0.f;
    #pragma unroll 8
    for (int m = 0; m < Cc; m++) s += ir[m] * W[(size_t)m * Cc + c];
    if (sel == 0) d_WqT[(size_t)c * Cc + n] = __float2bfloat16_rn(s);
    else d_WkvT[(size_t)c * 512 + (sel - 1) * Cc + n] = __float2bfloat16_rn(s);
    float pb = ir[c] * b[c];
    #pragma unroll
    for (int o = 16; o > 0; o >>= 1) pb += __shfl_down_sync(0xffffffffu, pb, o);
    if ((c & 31) == 0) red[c >> 5] = pb;
    __syncthreads();
    if (c == 0) {
        float t = 0.f;
        #pragma unroll
        for (int i = 0; i < 8; i++) t += red[i];
        d_bc[sel * Cc + n] = t + in_b[sel * Cc + n];
    }
}

// poskv[h][which*256+n] = sum_c pos_b[h][c]*WkvT[c][which*256+n] + bc[(which+1)*256+n]
__global__ void k_pos_proj(const float* __restrict__ pos_b) {
    int h = blockIdx.x, which = blockIdx.y, n = threadIdx.x;
    __shared__ float pb[Cc];
    pb[n] = pos_b[(size_t)h * Cc + n];
    __syncthreads();
    float s = d_bc[(which + 1) * Cc + n];
    #pragma unroll 8
    for (int c = 0; c < Cc; c++)
        s += pb[c] * __bfloat162float(d_WkvT[(size_t)c * 512 + which * 256 + n]);
    d_poskv[(size_t)h * 512 + which * 256 + n] = s;
}

// ---------------- transpose+convert list_b slice [C][M] fp32 -> [M][C] bf16 ----------
__global__ void k_b2bt(const float* __restrict__ src) {
    __shared__ float tile[32][33];
    int m0 = blockIdx.x * 32, c0 = blockIdx.y * 32;
    int tx = threadIdx.x;
    for (int i = threadIdx.y; i < 32; i += 8)
        tile[i][tx] = src[(size_t)(c0 + i) * MK + m0 + tx];
    __syncthreads();
    for (int i = threadIdx.y; i < 32; i += 8)
        d_btbf[(size_t)(m0 + i) * Cc + c0 + tx] = __float2bfloat16_rn(tile[tx][i]);
}

// ---------------- input transpose: (C,H,W) -> (HW, C) ----------------
__global__ void k_transpose_in(const float* __restrict__ a) {
    __shared__ float tile[32][33];
    int hw0 = blockIdx.x * 32;
    int c0  = blockIdx.y * 32;
    for (int i = threadIdx.y; i < 32; i += 8)
        tile[i][threadIdx.x] = a[(size_t)(c0 + i) * HWp + hw0 + threadIdx.x];
    __syncthreads();
    for (int i = threadIdx.y; i < 32; i += 8)
        d_at[(size_t)(hw0 + i) * Cc + c0 + threadIdx.x] = tile[threadIdx.x][i];
}

// ---------------- a_seq = bilinear(a_t) + pos_a  ->  bf16 ----------------
__global__ __launch_bounds__(256) void k_build_aseq(const float* __restrict__ pos_a, int ji) {
    int tx = threadIdx.x & 63;
    int ty = threadIdx.x >> 6;
    int p  = blockIdx.x * 4 + ty;
    int r = p / W2c, w = p % W2c;
    int q = ji * NPTS + p;
    int4 g = d_gidx[q];
    float2 wt = d_wxy[q];
    float w11 = wt.x * wt.y;
    float w01 = wt.x - w11;
    float w10 = wt.y - w11;
    float w00 = 1.f - wt.x - wt.y + w11;
    float4 v00 = ((const float4*)(d_at + (size_t)g.x * Cc))[tx];
    float4 v01 = ((const float4*)(d_at + (size_t)g.y * Cc))[tx];
    float4 v10 = ((const float4*)(d_at + (size_t)g.z * Cc))[tx];
    float4 v11 = ((const float4*)(d_at + (size_t)g.w * Cc))[tx];
    float4 pa  = ((const float4*)(pos_a + (size_t)r * Cc))[tx];
    float o0 = v00.x * w00 + v01.x * w01 + v10.x * w10 + v11.x * w11 + pa.x;
    float o1 = v00.y * w00 + v01.y * w01 + v10.y * w10 + v11.y * w11 + pa.y;
    float o2 = v00.z * w00 + v01.z * w01 + v10.z * w10 + v11.z * w11 + pa.z;
    float o3 = v00.w * w00 + v01.w * w01 + v10.w * w10 + v11.w * w11 + pa.w;
    int row = w * H1c + r;
    uint2 u = {bf2u(o0, o1), bf2u(o2, o3)};
    *(uint2*)(d_aseqbf + (size_t)row * Cc + tx * 4) = u;
}

// ================= cp.async pipelined bf16 mma GEMM — R13 engine, 4-stage ring =========
#define GSM_A(st)  ((st) * 10240)
#define GSM_B(st)  (40960 + (st) * 8704)
#define GSM_TOTAL  75776
template<int OUTMODE, int BIASMODE>
__global__ __launch_bounds__(256) void k_mma_gemm(const __nv_bfloat16* __restrict__ A,
                                                  const __nv_bfloat16* __restrict__ BT,
                                                  const float* __restrict__ bias,
                                                  __nv_bfloat16* __restrict__ outA,
                                                  __nv_bfloat16* __restrict__ outB,
                                                  float* __restrict__ restP,
                                                  int ldb, int biasld, int sidx_off) {
    extern __shared__ __align__(16) char gsm[];
    unsigned sbase = sptr(gsm);
    int t = threadIdx.x, lane = t & 31, warp = t >> 5;
    int m0 = blockIdx.x * 128, n0 = blockIdx.y * 128;
    int wm = (warp & 3) * 32;
    int wn = (warp >> 2) * 64;

    int am0 = t >> 2,            akq0 = (t & 3) * 8;
    int am1 = (t + 256) >> 2,    akq1 = (t & 3) * 8;
    int bk0 = t >> 4,            bn0 = (t & 15) * 8;
    int bk1 = (t + 256) >> 4,    bn1 = (t & 15) * 8;

    #define GISSUE(st, k0) do { \
        unsigned ab = sbase + GSM_A(st); \
        unsigned bb = sbase + GSM_B(st); \
        cp16(ab + (am0 * 40 + akq0) * 2, A + (size_t)(m0 + am0) * Cc + (k0) + akq0); \
        cp16(ab + (am1 * 40 + akq1) * 2, A + (size_t)(m0 + am1) * Cc + (k0) + akq1); \
        cp16(bb + (bk0 * 136 + bn0) * 2, BT + (size_t)((k0) + bk0) * ldb + n0 + bn0); \
        cp16(bb + (bk1 * 136 + bn1) * 2, BT + (size_t)((k0) + bk1) * ldb + n0 + bn1); \
    } while (0)

    float acc[2][8][4];
    #pragma unroll
    for (int i = 0; i < 2; i++)
        #pragma unroll
        for (int j = 0; j < 8; j++)
            #pragma unroll
            for (int q = 0; q < 4; q++) acc[i][j][q] = 0.f;

    GISSUE(0, 0);  CP_COMMIT();
    GISSUE(1, 32); CP_COMMIT();
    GISSUE(2, 64); CP_COMMIT();

    #pragma unroll 1
    for (int iter = 0; iter < 8; iter++) {
        if (iter < 6)       asm volatile("cp.async.wait_group 2;" ::: "memory");
        else if (iter == 6) asm volatile("cp.async.wait_group 1;" ::: "memory");
        else                asm volatile("cp.async.wait_group 0;" ::: "memory");
        __syncthreads();
        if (iter < 5) {
            GISSUE((iter + 3) & 3, (iter + 3) * 32);
            CP_COMMIT();
        }
        int s = iter & 3;
        unsigned ab = sbase + GSM_A(s);
        unsigned bb = sbase + GSM_B(s);
        #pragma unroll
        for (int kk = 0; kk < 32; kk += 16) {
            unsigned a[2][4], b[8][2];
            #pragma unroll
            for (int i = 0; i < 2; i++) {
                unsigned addr = ab + ((wm + i * 16 + (lane & 15)) * 40 + kk + (lane >> 4) * 8) * 2;
                LDMX4(a[i][0], a[i][1], a[i][2], a[i][3], addr);
            }
            #pragma unroll
            for (int j = 0; j < 4; j++) {
                unsigned addr = bb + ((kk + (lane & 15)) * 136 + wn + j * 16 + (lane >> 4) * 8) * 2;
                unsigned r0, r1, r2, r3;
                LDMX4T(r0, r1, r2, r3, addr);
                b[2 * j][0] = r0; b[2 * j][1] = r1;
                b[2 * j + 1][0] = r2; b[2 * j + 1][1] = r3;
            }
            #pragma unroll
            for (int i = 0; i < 2; i++)
                #pragma unroll
                for (int j = 0; j < 8; j++)
                    MMABF16(acc[i][j][0], acc[i][j][1], acc[i][j][2], acc[i][j][3],
                            a[i][0], a[i][1], a[i][2], a[i][3], b[j][0], b[j][1]);
        }
    }
    #undef GISSUE

    #pragma unroll
    for (int i = 0; i < 2; i++) {
        int mrow = m0 + wm + i * 16 + (lane >> 2);
        #pragma unroll
        for (int j = 0; j < 8; j++) {
            int n = n0 + wn + j * 8 + (lane & 3) * 2;
            float b0, b1, b2, b3;
            if (BIASMODE == 0) {
                b0 = bias[n]; b1 = bias[n + 1]; b2 = b0; b3 = b1;
            } else {
                int h0 = mrow / 400, h1 = (mrow + 8) / 400;
                b0 = bias[(size_t)h0 * biasld + n]; b1 = bias[(size_t)h0 * biasld + n + 1];
                b2 = bias[(size_t)h1 * biasld + n]; b3 = bias[(size_t)h1 * biasld + n + 1];
            }
            float v00 = acc[i][j][0] + b0, v01 = acc[i][j][1] + b1;
            float v10 = acc[i][j][2] + b2, v11 = acc[i][j][3] + b3;
            if (OUTMODE == 1) {
                __nv_bfloat16* o = (n < 256) ? outA : outB;
                int col = n & 255;
                *(__nv_bfloat162*)(o + (size_t)mrow * Cc + col) = __floats2bfloat162_rn(v00, v01);
                *(__nv_bfloat162*)(o + (size_t)(mrow + 8) * Cc + col) = __floats2bfloat162_rn(v10, v11);
            } else {
                int p0 = (mrow & 127) * W2c + (mrow >> 7);
                int p1 = ((mrow + 8) & 127) * W2c + ((mrow + 8) >> 7);
                int s0 = d_sidx[sidx_off + p0];
                int s1 = d_sidx[sidx_off + p1];
                red2(&restP[(size_t)s0 * Cc + n], v00, v01);
                red2(&restP[(size_t)s1 * Cc + n], v10, v11);
            }
        }
    }
}

// ---------------- tensor-core flash attention: grid (w=400, h=8), 128 threads ----------
__global__ __launch_bounds__(128) void k_attn_tc() {
    int w = blockIdx.x, h = blockIdx.y;
    int t = threadIdx.x, lane = t & 31, warp = t >> 5;
    __shared__ __align__(16) __nv_bfloat16 Qs[128 * 40];
    __shared__ __align__(16) __nv_bfloat16 Ks[64 * 40];
    __shared__ __align__(16) __nv_bfloat16 Vs[64 * 40];

    #pragma unroll
    for (int i = 0; i < 4; i++) {
        int slot = i * 128 + t;
        int row = slot >> 2, q4 = slot & 3;
        uint4 v = *(const uint4*)(d_qqbf + (size_t)(w * H1c + row) * Cc + h * DHc + q4 * 8);
        *(uint4*)(Qs + row * 40 + q4 * 8) = v;
    }
    #pragma unroll
    for (int i = 0; i < 2; i++) {
        int slot = i * 128 + t;
        int key = slot >> 2, q4 = slot & 3;
        size_t src = (size_t)(key * W2c + w) * Cc + h * DHc + q4 * 8;
        *(uint4*)(Ks + key * 40 + q4 * 8) = *(const uint4*)(d_kkbf + src);
        *(uint4*)(Vs + key * 40 + q4 * 8) = *(const uint4*)(d_vvbf + src);
    }
    __syncthreads();

    int wm = warp * 32;
    unsigned qa[2][2][4];
    #pragma unroll
    for (int i = 0; i < 2; i++)
        #pragma unroll
        for (int ks = 0; ks < 2; ks++) {
            unsigned addr = sptr(Qs + (wm + i * 16 + (lane & 15)) * 40 + ks * 16 + (lane >> 4) * 8);
            LDMX4(qa[i][ks][0], qa[i][ks][1], qa[i][ks][2], qa[i][ks][3], addr);
        }

    float sacc[2][8][4];
    #pragma unroll
    for (int i = 0; i < 2; i++)
        #pragma unroll
        for (int j = 0; j < 8; j++)
            #pragma unroll
            for (int q = 0; q < 4; q++) sacc[i][j][q] = 0.f;

    #pragma unroll
    for (int ks = 0; ks < 2; ks++) {
        #pragma unroll
        for (int ng = 0; ng < 4; ng++) {
            int row = ng * 16 + ((lane >> 4) & 1) * 8 + (lane & 7);
            int col = ((lane >> 3) & 1) * 8 + ks * 16;
            unsigned r0, r1, r2, r3;
            LDMX4(r0, r1, r2, r3, sptr(Ks + row * 40 + col));
            #pragma unroll
            for (int i = 0; i < 2; i++) {
                MMABF16(sacc[i][2 * ng][0], sacc[i][2 * ng][1], sacc[i][2 * ng][2], sacc[i][2 * ng][3],
                        qa[i][ks][0], qa[i][ks][1], qa[i][ks][2], qa[i][ks][3], r0, r1);
                MMABF16(sacc[i][2 * ng + 1][0], sacc[i][2 * ng + 1][1], sacc[i][2 * ng + 1][2], sacc[i][2 * ng + 1][3],
                        qa[i][ks][0], qa[i][ks][1], qa[i][ks][2], qa[i][ks][3], r2, r3);
            }
        }
    }

    const float sc = 0.17677669529663687f;  // 1/sqrt(32)
    float mx[2][2], ls[2][2];
    #pragma unroll
    for (int i = 0; i < 2; i++) {
        mx[i][0] = -INFINITY; mx[i][1] = -INFINITY;
        #pragma unroll
        for (int j = 0; j < 8; j++) {
            mx[i][0] = fmaxf(mx[i][0], fmaxf(sacc[i][j][0], sacc[i][j][1]));
            mx[i][1] = fmaxf(mx[i][1], fmaxf(sacc[i][j][2], sacc[i][j][3]));
        }
    }
    #pragma unroll
    for (int i = 0; i < 2; i++)
        #pragma unroll
        for (int s = 0; s < 2; s++) {
            float v = mx[i][s];
            v = fmaxf(v, __shfl_xor_sync(0xffffffffu, v, 1));
            v = fmaxf(v, __shfl_xor_sync(0xffffffffu, v, 2));
            mx[i][s] = v;
        }
    #pragma unroll
    for (int i = 0; i < 2; i++) {
        ls[i][0] = 0.f; ls[i][1] = 0.f;
        #pragma unroll
        for (int j = 0; j < 8; j++) {
            sacc[i][j][0] = __expf((sacc[i][j][0] - mx[i][0]) * sc);
            sacc[i][j][1] = __expf((sacc[i][j][1] - mx[i][0]) * sc);
            sacc[i][j][2] = __expf((sacc[i][j][2] - mx[i][1]) * sc);
            sacc[i][j][3] = __expf((sacc[i][j][3] - mx[i][1]) * sc);
            ls[i][0] += sacc[i][j][0] + sacc[i][j][1];
            ls[i][1] += sacc[i][j][2] + sacc[i][j][3];
        }
    }
    #pragma unroll
    for (int i = 0; i < 2; i++)
        #pragma unroll
        for (int s = 0; s < 2; s++) {
            float v = ls[i][s];
            v += __shfl_xor_sync(0xffffffffu, v, 1);
            v += __shfl_xor_sync(0xffffffffu, v, 2);
            ls[i][s] = v;
        }

    unsigned pa[2][4][4];
    #pragma unroll
    for (int i = 0; i < 2; i++)
        #pragma unroll
        for (int s = 0; s < 4; s++) {
            pa[i][s][0] = bf2u(sacc[i][2 * s][0],     sacc[i][2 * s][1]);
            pa[i][s][1] = bf2u(sacc[i][2 * s][2],     sacc[i][2 * s][3]);
            pa[i][s][2] = bf2u(sacc[i][2 * s + 1][0], sacc[i][2 * s + 1][1]);
            pa[i][s][3] = bf2u(sacc[i][2 * s + 1][2], sacc[i][2 * s + 1][3]);
        }

    float oacc[2][4][4];
    #pragma unroll
    for (int i = 0; i < 2; i++)
        #pragma unroll
        for (int j = 0; j < 4; j++)
            #pragma unroll
            for (int q = 0; q < 4; q++) oacc[i][j][q] = 0.f;
    #pragma unroll
    for (int s = 0; s < 4; s++) {
        #pragma unroll
        for (int jn = 0; jn < 2; jn++) {
            unsigned r0, r1, r2, r3;
            LDMX4T(r0, r1, r2, r3,
                   sptr(Vs + (s * 16 + (lane & 15)) * 40 + jn * 16 + (lane >> 4) * 8));
            #pragma unroll
            for (int i = 0; i < 2; i++) {
                MMABF16(oacc[i][2 * jn][0], oacc[i][2 * jn][1], oacc[i][2 * jn][2], oacc[i][2 * jn][3],
                        pa[i][s][0], pa[i][s][1], pa[i][s][2], pa[i][s][3], r0, r1);
                MMABF16(oacc[i][2 * jn + 1][0], oacc[i][2 * jn + 1][1], oacc[i][2 * jn + 1][2], oacc[i][2 * jn + 1][3],
                        pa[i][s][0], pa[i][s][1], pa[i][s][2], pa[i][s][3], r2, r3);
            }
        }
    }

    #pragma unroll
    for (int i = 0; i < 2; i++) {
        float inv0 = 1.f / ls[i][0], inv1 = 1.f / ls[i][1];
        int r0w = w * H1c + wm + i * 16 + (lane >> 2);
        #pragma unroll
        for (int j = 0; j < 4; j++) {
            int col = h * DHc + j * 8 + (lane & 3) * 2;
            *(__nv_bfloat162*)(d_obf + (size_t)r0w * Cc + col) =
                __floats2bfloat162_rn(oacc[i][j][0] * inv0, oacc[i][j][1] * inv0);
            *(__nv_bfloat162*)(d_obf + (size_t)(r0w + 8) * Cc + col) =
                __floats2bfloat162_rn(oacc[i][j][2] * inv1, oacc[i][j][3] * inv1);
        }
    }
}

// ---------------- update (pass 1): at += rest/cnt ----------------
__global__ void k_update() {
    int hw = blockIdx.x, c = threadIdx.x;
    float cnt = d_cnt[hw];
    cnt = (cnt == 0.f) ? 1.f : cnt;
    size_t idx = (size_t)hw * Cc + c;
    d_at[idx] += d_rest[idx] / cnt;
}

// ---------------- final: out[c][hw] = at[hw][c] + 2*rest2[hw][c]/cnt2[hw] ----------------
__global__ void k_writeout(float* __restrict__ out) {
    __shared__ float tile[32][33];
    int hw0 = blockIdx.x * 32;
    int c0  = blockIdx.y * 32;
    int tx = threadIdx.x;
    for (int i = threadIdx.y; i < 32; i += 8) {
        float cnt = d_cnt2[hw0 + i];
        cnt = (cnt == 0.f) ? 1.f : cnt;
        size_t idx = (size_t)(hw0 + i) * Cc + c0 + tx;
        tile[i][tx] = d_at[idx] + 2.f * d_rest2[idx] / cnt;
    }
    __syncthreads();
    for (int i = threadIdx.y; i < 32; i += 8)
        out[(size_t)(c0 + i) * HWp + hw0 + tx] = tile[tx][i];
}

// ---------------- host launcher (single stream) ----------------
extern "C" void kernel_launch(void* const* d_in, const int* in_sizes, int n_in,
                              void* d_out, int out_size) {
    const float* list_a = (const float*)d_in[0];
    const float* list_b = (const float*)d_in[1];
    const float* rots   = (const float*)d_in[3];
    const float* fxs    = (const float*)d_in[5];
    const float* cxs    = (const float*)d_in[6];
    const float* pos_a  = (const float*)d_in[7];
    const float* pos_b  = (const float*)d_in[8];
    const float* Wq     = (const float*)d_in[9];
    const float* bq     = (const float*)d_in[10];
    const float* Wk     = (const float*)d_in[11];
    const float* bk     = (const float*)d_in[12];
    const float* Wv     = (const float*)d_in[13];
    const float* bv     = (const float*)d_in[14];
    const float* in_w   = (const float*)d_in[15];
    const float* in_b   = (const float*)d_in[16];
    const float* out_w  = (const float*)d_in[17];
    const float* out_b  = (const float*)d_in[18];
    float* out = (float*)d_out;

    float *p_bc, *p_poskv, *p_rest, *p_rest2;
    __nv_bfloat16 *p_aseqbf, *p_btbf, *p_qqbf, *p_kkbf, *p_vvbf, *p_obf,
                  *p_WqT, *p_WkvT, *p_outwT;
    cudaGetSymbolAddress((void**)&p_bc,     d_bc);
    cudaGetSymbolAddress((void**)&p_poskv,  d_poskv);
    cudaGetSymbolAddress((void**)&p_rest,   d_rest);
    cudaGetSymbolAddress((void**)&p_rest2,  d_rest2);
    cudaGetSymbolAddress((void**)&p_aseqbf, d_aseqbf);
    cudaGetSymbolAddress((void**)&p_btbf,   d_btbf);
    cudaGetSymbolAddress((void**)&p_qqbf,   d_qqbf);
    cudaGetSymbolAddress((void**)&p_kkbf,   d_kkbf);
    cudaGetSymbolAddress((void**)&p_vvbf,   d_vvbf);
    cudaGetSymbolAddress((void**)&p_obf,    d_obf);
    cudaGetSymbolAddress((void**)&p_WqT,    d_WqT);
    cudaGetSymbolAddress((void**)&p_WkvT,   d_WkvT);
    cudaGetSymbolAddress((void**)&p_outwT,  d_outwT);

    cudaFuncSetAttribute(k_mma_gemm<1, 0>, cudaFuncAttributeMaxDynamicSharedMemorySize, GSM_TOTAL);
    cudaFuncSetAttribute(k_mma_gemm<1, 1>, cudaFuncAttributeMaxDynamicSharedMemorySize, GSM_TOTAL);
    cudaFuncSetAttribute(k_mma_gemm<2, 0>, cudaFuncAttributeMaxDynamicSharedMemorySize, GSM_TOTAL);

    k_zero<<<4096, 256>>>();                                                         // 0
    k_coords_all<<<dim3((NPTS + 255) / 256, 2), 256>>>(rots, fxs, cxs);              // 1
    k_combine_all<<<dim3(Cc, 4), Cc>>>(Wq, Wk, Wv, in_w, bq, bk, bv, in_b, out_w);   // 2
    k_pos_proj<<<dim3(H2c, 2), Cc>>>(pos_b);                                         // 3
    k_b2bt<<<dim3(MK / 32, Cc / 32), dim3(32, 8)>>>(list_b);                         // 4
    k_mma_gemm<1, 1><<<dim3(MK / 128, 4), 256, GSM_TOTAL>>>(                         // 5 <- profiled
        p_btbf, p_WkvT, p_poskv, p_kkbf, p_vvbf, nullptr, 512, 512, 0);
    k_transpose_in<<<dim3(HWp / 32, Cc / 32), dim3(32, 8)>>>(list_a);                // 6

    for (int ji = 0; ji < 2; ji++) {
        if (ji == 1) {
            k_b2bt<<<dim3(MK / 32, Cc / 32), dim3(32, 8)>>>(list_b + (size_t)3 * Cc * MK);
            k_mma_gemm<1, 1><<<dim3(MK / 128, 4), 256, GSM_TOTAL>>>(
                p_btbf, p_WkvT, p_poskv, p_kkbf, p_vvbf, nullptr, 512, 512, 0);
        }
        k_build_aseq<<<NPTS / 4, 256>>>(pos_a, ji);
        k_mma_gemm<1, 0><<<dim3(MQ / 128, 2), 256, GSM_TOTAL>>>(
            p_aseqbf, p_WqT, p_bc, p_qqbf, p_qqbf, nullptr, 256, 0, 0);
        k_attn_tc<<<dim3(W2c, 8), 128>>>();
        k_mma_gemm<2, 0><<<dim3(MQ / 128, 2), 256, GSM_TOTAL>>>(
            p_obf, p_outwT, out_b, nullptr, nullptr, ji == 0 ? p_rest : p_rest2,
            256, 0, ji * NPTS);
        if (ji == 0) k_update<<<HWp, Cc>>>();
    }
    k_writeout<<<dim3(HWp / 32, Cc / 32), dim3(32, 8)>>>(out);
}

// round 17
// speedup vs baseline: 1.0660x; 1.0350x over previous
#include <cuda_runtime.h>
#include <cuda_bf16.h>
#include <math.h>

// ---------------- problem constants ----------------
#define Cc    256
#define HWp   16384      // 128*128
#define Ww    128
#define H1c   128
#define H2c   64
#define W2c   400
#define NPTS  (H1c*W2c)  // 51200
#define MQ    NPTS
#define MK    (H2c*W2c)  // 25600
#define DHc   32

// ---------------- scratch (device globals; no runtime alloc) ----------------
__device__ float  d_at[HWp*Cc];             // working image, HWC layout
__device__ __nv_bfloat16 d_aseqbf[MQ*Cc];
__device__ __nv_bfloat16 d_btbf[MK*Cc];     // list_b slice transposed to [M][K] bf16
__device__ __nv_bfloat16 d_qqbf[MQ*Cc];
__device__ __nv_bfloat16 d_kkbf[MK*Cc];
__device__ __nv_bfloat16 d_vvbf[MK*Cc];
__device__ __nv_bfloat16 d_obf[MQ*Cc];
__device__ float  d_rest[HWp*Cc];
__device__ float  d_rest2[HWp*Cc];
__device__ float  d_cnt[HWp];
__device__ float  d_cnt2[HWp];
__device__ int4   d_gidx[2*NPTS];
__device__ float2 d_wxy[2*NPTS];
__device__ int    d_sidx[2*NPTS];
__device__ float  d_bc[3*Cc];               // combined biases
__device__ __nv_bfloat16 d_WqT[Cc*Cc];      // combined Q weight bf16 K-major [k][n]
__device__ __nv_bfloat16 d_WkvT[Cc*2*Cc];   // stacked K|V weights bf16 K-major [k][512]
__device__ __nv_bfloat16 d_outwT[Cc*Cc];    // out_w bf16 K-major [k][n]
__device__ float  d_poskv[H2c*2*Cc];        // stacked pos bias [h][512] (K|V)

__device__ __forceinline__ unsigned sptr(const void* p) {
    return (unsigned)__cvta_generic_to_shared(p);
}
__device__ __forceinline__ unsigned bf2u(float a, float b) {
    __nv_bfloat162 t = __floats2bfloat162_rn(a, b);
    return *(unsigned*)&t;
}
// -------- vectorized global reduction (sm_90+) --------
__device__ __forceinline__ void red2(float* p, float a, float b) {
    asm volatile("red.global.add.v2.f32 [%0], {%1, %2};" :: "l"(p), "f"(a), "f"(b) : "memory");
}
// -------- cp.async --------
__device__ __forceinline__ void cp16(unsigned saddr, const void* g) {
    asm volatile("cp.async.ca.shared.global [%0], [%1], 16;" :: "r"(saddr), "l"(g));
}
#define CP_COMMIT() asm volatile("cp.async.commit_group;" ::: "memory")

#define LDMX4(r0,r1,r2,r3,addr) \
    asm volatile("ldmatrix.sync.aligned.m8n8.x4.shared.b16 {%0,%1,%2,%3},[%4];" \
        : "=r"(r0),"=r"(r1),"=r"(r2),"=r"(r3) : "r"(addr))
#define LDMX4T(r0,r1,r2,r3,addr) \
    asm volatile("ldmatrix.sync.aligned.m8n8.x4.trans.shared.b16 {%0,%1,%2,%3},[%4];" \
        : "=r"(r0),"=r"(r1),"=r"(r2),"=r"(r3) : "r"(addr))
#define MMABF16(c0,c1,c2,c3,a0,a1,a2,a3,b0,b1) \
    asm volatile("mma.sync.aligned.m16n8k16.row.col.f32.bf16.bf16.f32 " \
        "{%0,%1,%2,%3},{%4,%5,%6,%7},{%8,%9},{%0,%1,%2,%3};" \
        : "+f"(c0),"+f"(c1),"+f"(c2),"+f"(c3) \
        : "r"(a0),"r"(a1),"r"(a2),"r"(a3),"r"(b0),"r"(b1))

// ---------------- zero rest/rest2/cnt/cnt2 ----------------
__global__ void k_zero() {
    size_t i = (size_t)blockIdx.x * 256 + threadIdx.x;
    float4 z = make_float4(0.f, 0.f, 0.f, 0.f);
    ((float4*)d_rest)[i]  = z;      // grid covers HWp*Cc/4 exactly
    ((float4*)d_rest2)[i] = z;
    if (i < HWp / 4) { ((float4*)d_cnt)[i] = z; ((float4*)d_cnt2)[i] = z; }
}

// ---------------- coords for BOTH passes (+ scatter counts) ----------------
__global__ void k_coords_all(const float* __restrict__ rots, const float* __restrict__ fxs,
                             const float* __restrict__ cxs) {
    int p = blockIdx.x * blockDim.x + threadIdx.x;
    int ji = blockIdx.y;
    if (p >= NPTS) return;
    int j = ji * 3;  // cams 0 and 3
    int r = p / W2c, w = p % W2c;
    float fx = fxs[j], cx = cxs[j];
    float cth = rots[j * 9 + 0];
    float sth = rots[j * 9 + 3];
    float ang = atanf((w * 2.0f + 1.0f - cx) / fx);
    float cA = cosf(ang), sA = sinf(ang);
    float ca = sth * cA - cth * sA;
    float sa = cth * cA + sth * sA;
    float rmax = sqrtf(64.f * 64.f + 64.f * 64.f);
    float rad = ((float)r / 127.0f) * rmax;
    float x = 64.f + rad * ca;
    float y = 64.f - rad * sa;
    float xc = fminf(fmaxf(x, 0.f), 127.f);
    float yc = fminf(fmaxf(y, 0.f), 127.f);
    float x0 = floorf(xc), y0 = floorf(yc);
    float x1 = fminf(x0 + 1.f, 127.f), y1 = fminf(y0 + 1.f, 127.f);
    int x0i = (int)x0, x1i = (int)x1, y0i = (int)y0, y1i = (int)y1;
    int q = ji * NPTS + p;
    d_gidx[q] = make_int4(y0i * Ww + x0i, y0i * Ww + x1i, y1i * Ww + x0i, y1i * Ww + x1i);
    d_wxy[q]  = make_float2(xc - x0, yc - y0);
    int xi = (int)fminf(fmaxf(rintf(x), 0.f), 127.f);
    int yi = (int)fminf(fmaxf(rintf(y), 0.f), 127.f);
    int si = yi * Ww + xi;
    d_sidx[q] = si;
    atomicAdd((ji == 0 ? d_cnt : d_cnt2) + si, 1.0f);
}

// ---------------- combined weights + bias + bf16 K-major transposes ----------------
__global__ void k_combine_all(const float* __restrict__ Wq, const float* __restrict__ Wk,
                              const float* __restrict__ Wv, const float* __restrict__ in_w,
                              const float* __restrict__ bq, const float* __restrict__ bk,
                              const float* __restrict__ bv, const float* __restrict__ in_b,
                              const float* __restrict__ out_w) {
    int n = blockIdx.x, sel = blockIdx.y, c = threadIdx.x;
    if (sel == 3) {
        d_outwT[(size_t)c * Cc + n] = __float2bfloat16_rn(out_w[(size_t)n * Cc + c]);
        return;
    }
    const float* W = (sel == 0) ? Wq : ((sel == 1) ? Wk : Wv);
    const float* b = (sel == 0) ? bq : ((sel == 1) ? bk : bv);
    __shared__ float ir[Cc];
    __shared__ float red[8];
    ir[c] = in_w[(size_t)(sel * Cc + n) * Cc + c];
    __syncthreads();
    float s = 0.f;
    #pragma unroll 8
    for (int m = 0; m < Cc; m++) s += ir[m] * W[(size_t)m * Cc + c];
    if (sel == 0) d_WqT[(size_t)c * Cc + n] = __float2bfloat16_rn(s);
    else d_WkvT[(size_t)c * 512 + (sel - 1) * Cc + n] = __float2bfloat16_rn(s);
    float pb = ir[c] * b[c];
    #pragma unroll
    for (int o = 16; o > 0; o >>= 1) pb += __shfl_down_sync(0xffffffffu, pb, o);
    if ((c & 31) == 0) red[c >> 5] = pb;
    __syncthreads();
    if (c == 0) {
        float t = 0.f;
        #pragma unroll
        for (int i = 0; i < 8; i++) t += red[i];
        d_bc[sel * Cc + n] = t + in_b[sel * Cc + n];
    }
}

// poskv[h][which*256+n] = sum_c pos_b[h][c]*WkvT[c][which*256+n] + bc[(which+1)*256+n]
__global__ void k_pos_proj(const float* __restrict__ pos_b) {
    int h = blockIdx.x, which = blockIdx.y, n = threadIdx.x;
    __shared__ float pb[Cc];
    pb[n] = pos_b[(size_t)h * Cc + n];
    __syncthreads();
    float s = d_bc[(which + 1) * Cc + n];
    #pragma unroll 8
    for (int c = 0; c < Cc; c++)
        s += pb[c] * __bfloat162float(d_WkvT[(size_t)c * 512 + which * 256 + n]);
    d_poskv[(size_t)h * 512 + which * 256 + n] = s;
}

// ---------------- transpose+convert list_b slice [C][M] fp32 -> [M][C] bf16 ----------
__global__ void k_b2bt(const float* __restrict__ src) {
    __shared__ float tile[32][33];
    int m0 = blockIdx.x * 32, c0 = blockIdx.y * 32;
    int tx = threadIdx.x;
    for (int i = threadIdx.y; i < 32; i += 8)
        tile[i][tx] = src[(size_t)(c0 + i) * MK + m0 + tx];
    __syncthreads();
    for (int i = threadIdx.y; i < 32; i += 8)
        d_btbf[(size_t)(m0 + i) * Cc + c0 + tx] = __float2bfloat16_rn(tile[tx][i]);
}

// ---------------- input transpose: (C,H,W) -> (HW, C) ----------------
__global__ void k_transpose_in(const float* __restrict__ a) {
    __shared__ float tile[32][33];
    int hw0 = blockIdx.x * 32;
    int c0  = blockIdx.y * 32;
    for (int i = threadIdx.y; i < 32; i += 8)
        tile[i][threadIdx.x] = a[(size_t)(c0 + i) * HWp + hw0 + threadIdx.x];
    __syncthreads();
    for (int i = threadIdx.y; i < 32; i += 8)
        d_at[(size_t)(hw0 + i) * Cc + c0 + threadIdx.x] = tile[threadIdx.x][i];
}

// ---------------- a_seq = bilinear(a_t) + pos_a  ->  bf16 ----------------
__global__ __launch_bounds__(256) void k_build_aseq(const float* __restrict__ pos_a, int ji) {
    int tx = threadIdx.x & 63;
    int ty = threadIdx.x >> 6;
    int p  = blockIdx.x * 4 + ty;
    int r = p / W2c, w = p % W2c;
    int q = ji * NPTS + p;
    int4 g = d_gidx[q];
    float2 wt = d_wxy[q];
    float w11 = wt.x * wt.y;
    float w01 = wt.x - w11;
    float w10 = wt.y - w11;
    float w00 = 1.f - wt.x - wt.y + w11;
    float4 v00 = ((const float4*)(d_at + (size_t)g.x * Cc))[tx];
    float4 v01 = ((const float4*)(d_at + (size_t)g.y * Cc))[tx];
    float4 v10 = ((const float4*)(d_at + (size_t)g.z * Cc))[tx];
    float4 v11 = ((const float4*)(d_at + (size_t)g.w * Cc))[tx];
    float4 pa  = ((const float4*)(pos_a + (size_t)r * Cc))[tx];
    float o0 = v00.x * w00 + v01.x * w01 + v10.x * w10 + v11.x * w11 + pa.x;
    float o1 = v00.y * w00 + v01.y * w01 + v10.y * w10 + v11.y * w11 + pa.y;
    float o2 = v00.z * w00 + v01.z * w01 + v10.z * w10 + v11.z * w11 + pa.z;
    float o3 = v00.w * w00 + v01.w * w01 + v10.w * w10 + v11.w * w11 + pa.w;
    int row = w * H1c + r;
    uint2 u = {bf2u(o0, o1), bf2u(o2, o3)};
    *(uint2*)(d_aseqbf + (size_t)row * Cc + tx * 4) = u;
}

// ================= cp.async pipelined bf16 mma GEMM (R13 champion engine) =============
#define GSM_A(st)  ((st) * 10240)
#define GSM_B(st)  (30720 + (st) * 8704)
#define GSM_TOTAL  56832
template<int OUTMODE, int BIASMODE>
__global__ __launch_bounds__(256) void k_mma_gemm(const __nv_bfloat16* __restrict__ A,
                                                  const __nv_bfloat16* __restrict__ BT,
                                                  const float* __restrict__ bias,
                                                  __nv_bfloat16* __restrict__ outA,
                                                  __nv_bfloat16* __restrict__ outB,
                                                  float* __restrict__ restP,
                                                  int ldb, int biasld, int sidx_off) {
    extern __shared__ __align__(16) char gsm[];
    unsigned sbase = sptr(gsm);
    int t = threadIdx.x, lane = t & 31, warp = t >> 5;
    int m0 = blockIdx.x * 128, n0 = blockIdx.y * 128;
    int wm = (warp & 3) * 32;
    int wn = (warp >> 2) * 64;

    int am0 = t >> 2,            akq0 = (t & 3) * 8;
    int am1 = (t + 256) >> 2,    akq1 = (t & 3) * 8;
    int bk0 = t >> 4,            bn0 = (t & 15) * 8;
    int bk1 = (t + 256) >> 4,    bn1 = (t & 15) * 8;

    #define GISSUE(st, k0) do { \
        unsigned ab = sbase + GSM_A(st); \
        unsigned bb = sbase + GSM_B(st); \
        cp16(ab + (am0 * 40 + akq0) * 2, A + (size_t)(m0 + am0) * Cc + (k0) + akq0); \
        cp16(ab + (am1 * 40 + akq1) * 2, A + (size_t)(m0 + am1) * Cc + (k0) + akq1); \
        cp16(bb + (bk0 * 136 + bn0) * 2, BT + (size_t)((k0) + bk0) * ldb + n0 + bn0); \
        cp16(bb + (bk1 * 136 + bn1) * 2, BT + (size_t)((k0) + bk1) * ldb + n0 + bn1); \
    } while (0)

    float acc[2][8][4];
    #pragma unroll
    for (int i = 0; i < 2; i++)
        #pragma unroll
        for (int j = 0; j < 8; j++)
            #pragma unroll
            for (int q = 0; q < 4; q++) acc[i][j][q] = 0.f;

    GISSUE(0, 0);  CP_COMMIT();
    GISSUE(1, 32); CP_COMMIT();

    #pragma unroll 1
    for (int iter = 0; iter < 8; iter++) {
        if (iter < 7) asm volatile("cp.async.wait_group 1;" ::: "memory");
        else          asm volatile("cp.async.wait_group 0;" ::: "memory");
        __syncthreads();
        if (iter < 6) {
            int st = iter + 2;
            int buf = st - (st >= 6 ? 6 : (st >= 3 ? 3 : 0));
            GISSUE(buf, st * 32);
            CP_COMMIT();
        }
        int s = iter - (iter >= 6 ? 6 : (iter >= 3 ? 3 : 0));
        unsigned ab = sbase + GSM_A(s);
        unsigned bb = sbase + GSM_B(s);
        #pragma unroll
        for (int kk = 0; kk < 32; kk += 16) {
            unsigned a[2][4], b[8][2];
            #pragma unroll
            for (int i = 0; i < 2; i++) {
                unsigned addr = ab + ((wm + i * 16 + (lane & 15)) * 40 + kk + (lane >> 4) * 8) * 2;
                LDMX4(a[i][0], a[i][1], a[i][2], a[i][3], addr);
            }
            #pragma unroll
            for (int j = 0; j < 4; j++) {
                unsigned addr = bb + ((kk + (lane & 15)) * 136 + wn + j * 16 + (lane >> 4) * 8) * 2;
                unsigned r0, r1, r2, r3;
                LDMX4T(r0, r1, r2, r3, addr);
                b[2 * j][0] = r0; b[2 * j][1] = r1;
                b[2 * j + 1][0] = r2; b[2 * j + 1][1] = r3;
            }
            #pragma unroll
            for (int i = 0; i < 2; i++)
                #pragma unroll
                for (int j = 0; j < 8; j++)
                    MMABF16(acc[i][j][0], acc[i][j][1], acc[i][j][2], acc[i][j][3],
                            a[i][0], a[i][1], a[i][2], a[i][3], b[j][0], b[j][1]);
        }
    }
    #undef GISSUE

    #pragma unroll
    for (int i = 0; i < 2; i++) {
        int mrow = m0 + wm + i * 16 + (lane >> 2);
        #pragma unroll
        for (int j = 0; j < 8; j++) {
            int n = n0 + wn + j * 8 + (lane & 3) * 2;
            float b0, b1, b2, b3;
            if (BIASMODE == 0) {
                b0 = bias[n]; b1 = bias[n + 1]; b2 = b0; b3 = b1;
            } else {
                int h0 = mrow / 400, h1 = (mrow + 8) / 400;
                b0 = bias[(size_t)h0 * biasld + n]; b1 = bias[(size_t)h0 * biasld + n + 1];
                b2 = bias[(size_t)h1 * biasld + n]; b3 = bias[(size_t)h1 * biasld + n + 1];
            }
            float v00 = acc[i][j][0] + b0, v01 = acc[i][j][1] + b1;
            float v10 = acc[i][j][2] + b2, v11 = acc[i][j][3] + b3;
            if (OUTMODE == 1) {
                __nv_bfloat16* o = (n < 256) ? outA : outB;
                int col = n & 255;
                *(__nv_bfloat162*)(o + (size_t)mrow * Cc + col) = __floats2bfloat162_rn(v00, v01);
                *(__nv_bfloat162*)(o + (size_t)(mrow + 8) * Cc + col) = __floats2bfloat162_rn(v10, v11);
            } else {
                int p0 = (mrow & 127) * W2c + (mrow >> 7);
                int p1 = ((mrow + 8) & 127) * W2c + ((mrow + 8) >> 7);
                int s0 = d_sidx[sidx_off + p0];
                int s1 = d_sidx[sidx_off + p1];
                red2(&restP[(size_t)s0 * Cc + n], v00, v01);
                red2(&restP[(size_t)s1 * Cc + n], v10, v11);
            }
        }
    }
}

// ---------------- tensor-core flash attention: grid (w=400, h=8), 128 threads ----------
__global__ __launch_bounds__(128) void k_attn_tc() {
    int w = blockIdx.x, h = blockIdx.y;
    int t = threadIdx.x, lane = t & 31, warp = t >> 5;
    __shared__ __align__(16) __nv_bfloat16 Qs[128 * 40];
    __shared__ __align__(16) __nv_bfloat16 Ks[64 * 40];
    __shared__ __align__(16) __nv_bfloat16 Vs[64 * 40];

    #pragma unroll
    for (int i = 0; i < 4; i++) {
        int slot = i * 128 + t;
        int row = slot >> 2, q4 = slot & 3;
        uint4 v = *(const uint4*)(d_qqbf + (size_t)(w * H1c + row) * Cc + h * DHc + q4 * 8);
        *(uint4*)(Qs + row * 40 + q4 * 8) = v;
    }
    #pragma unroll
    for (int i = 0; i < 2; i++) {
        int slot = i * 128 + t;
        int key = slot >> 2, q4 = slot & 3;
        size_t src = (size_t)(key * W2c + w) * Cc + h * DHc + q4 * 8;
        *(uint4*)(Ks + key * 40 + q4 * 8) = *(const uint4*)(d_kkbf + src);
        *(uint4*)(Vs + key * 40 + q4 * 8) = *(const uint4*)(d_vvbf + src);
    }
    __syncthreads();

    int wm = warp * 32;
    unsigned qa[2][2][4];
    #pragma unroll
    for (int i = 0; i < 2; i++)
        #pragma unroll
        for (int ks = 0; ks < 2; ks++) {
            unsigned addr = sptr(Qs + (wm + i * 16 + (lane & 15)) * 40 + ks * 16 + (lane >> 4) * 8);
            LDMX4(qa[i][ks][0], qa[i][ks][1], qa[i][ks][2], qa[i][ks][3], addr);
        }

    float sacc[2][8][4];
    #pragma unroll
    for (int i = 0; i < 2; i++)
        #pragma unroll
        for (int j = 0; j < 8; j++)
            #pragma unroll
            for (int q = 0; q < 4; q++) sacc[i][j][q] = 0.f;

    #pragma unroll
    for (int ks = 0; ks < 2; ks++) {
        #pragma unroll
        for (int ng = 0; ng < 4; ng++) {
            int row = ng * 16 + ((lane >> 4) & 1) * 8 + (lane & 7);
            int col = ((lane >> 3) & 1) * 8 + ks * 16;
            unsigned r0, r1, r2, r3;
            LDMX4(r0, r1, r2, r3, sptr(Ks + row * 40 + col));
            #pragma unroll
            for (int i = 0; i < 2; i++) {
                MMABF16(sacc[i][2 * ng][0], sacc[i][2 * ng][1], sacc[i][2 * ng][2], sacc[i][2 * ng][3],
                        qa[i][ks][0], qa[i][ks][1], qa[i][ks][2], qa[i][ks][3], r0, r1);
                MMABF16(sacc[i][2 * ng + 1][0], sacc[i][2 * ng + 1][1], sacc[i][2 * ng + 1][2], sacc[i][2 * ng + 1][3],
                        qa[i][ks][0], qa[i][ks][1], qa[i][ks][2], qa[i][ks][3], r2, r3);
            }
        }
    }

    const float sc = 0.17677669529663687f;  // 1/sqrt(32)
    float mx[2][2], ls[2][2];
    #pragma unroll
    for (int i = 0; i < 2; i++) {
        mx[i][0] = -INFINITY; mx[i][1] = -INFINITY;
        #pragma unroll
        for (int j = 0; j < 8; j++) {
            mx[i][0] = fmaxf(mx[i][0], fmaxf(sacc[i][j][0], sacc[i][j][1]));
            mx[i][1] = fmaxf(mx[i][1], fmaxf(sacc[i][j][2], sacc[i][j][3]));
        }
    }
    #pragma unroll
    for (int i = 0; i < 2; i++)
        #pragma unroll
        for (int s = 0; s < 2; s++) {
            float v = mx[i][s];
            v = fmaxf(v, __shfl_xor_sync(0xffffffffu, v, 1));
            v = fmaxf(v, __shfl_xor_sync(0xffffffffu, v, 2));
            mx[i][s] = v;
        }
    #pragma unroll
    for (int i = 0; i < 2; i++) {
        ls[i][0] = 0.f; ls[i][1] = 0.f;
        #pragma unroll
        for (int j = 0; j < 8; j++) {
            sacc[i][j][0] = __expf((sacc[i][j][0] - mx[i][0]) * sc);
            sacc[i][j][1] = __expf((sacc[i][j][1] - mx[i][0]) * sc);
            sacc[i][j][2] = __expf((sacc[i][j][2] - mx[i][1]) * sc);
            sacc[i][j][3] = __expf((sacc[i][j][3] - mx[i][1]) * sc);
            ls[i][0] += sacc[i][j][0] + sacc[i][j][1];
            ls[i][1] += sacc[i][j][2] + sacc[i][j][3];
        }
    }
    #pragma unroll
    for (int i = 0; i < 2; i++)
        #pragma unroll
        for (int s = 0; s < 2; s++) {
            float v = ls[i][s];
            v += __shfl_xor_sync(0xffffffffu, v, 1);
            v += __shfl_xor_sync(0xffffffffu, v, 2);
            ls[i][s] = v;
        }

    unsigned pa[2][4][4];
    #pragma unroll
    for (int i = 0; i < 2; i++)
        #pragma unroll
        for (int s = 0; s < 4; s++) {
            pa[i][s][0] = bf2u(sacc[i][2 * s][0],     sacc[i][2 * s][1]);
            pa[i][s][1] = bf2u(sacc[i][2 * s][2],     sacc[i][2 * s][3]);
            pa[i][s][2] = bf2u(sacc[i][2 * s + 1][0], sacc[i][2 * s + 1][1]);
            pa[i][s][3] = bf2u(sacc[i][2 * s + 1][2], sacc[i][2 * s + 1][3]);
        }

    float oacc[2][4][4];
    #pragma unroll
    for (int i = 0; i < 2; i++)
        #pragma unroll
        for (int j = 0; j < 4; j++)
            #pragma unroll
            for (int q = 0; q < 4; q++) oacc[i][j][q] = 0.f;
    #pragma unroll
    for (int s = 0; s < 4; s++) {
        #pragma unroll
        for (int jn = 0; jn < 2; jn++) {
            unsigned r0, r1, r2, r3;
            LDMX4T(r0, r1, r2, r3,
                   sptr(Vs + (s * 16 + (lane & 15)) * 40 + jn * 16 + (lane >> 4) * 8));
            #pragma unroll
            for (int i = 0; i < 2; i++) {
                MMABF16(oacc[i][2 * jn][0], oacc[i][2 * jn][1], oacc[i][2 * jn][2], oacc[i][2 * jn][3],
                        pa[i][s][0], pa[i][s][1], pa[i][s][2], pa[i][s][3], r0, r1);
                MMABF16(oacc[i][2 * jn + 1][0], oacc[i][2 * jn + 1][1], oacc[i][2 * jn + 1][2], oacc[i][2 * jn + 1][3],
                        pa[i][s][0], pa[i][s][1], pa[i][s][2], pa[i][s][3], r2, r3);
            }
        }
    }

    #pragma unroll
    for (int i = 0; i < 2; i++) {
        float inv0 = 1.f / ls[i][0], inv1 = 1.f / ls[i][1];
        int r0w = w * H1c + wm + i * 16 + (lane >> 2);
        #pragma unroll
        for (int j = 0; j < 4; j++) {
            int col = h * DHc + j * 8 + (lane & 3) * 2;
            *(__nv_bfloat162*)(d_obf + (size_t)r0w * Cc + col) =
                __floats2bfloat162_rn(oacc[i][j][0] * inv0, oacc[i][j][1] * inv0);
            *(__nv_bfloat162*)(d_obf + (size_t)(r0w + 8) * Cc + col) =
                __floats2bfloat162_rn(oacc[i][j][2] * inv1, oacc[i][j][3] * inv1);
        }
    }
}

// ---------------- update (pass 1): at += rest/cnt  (float4 vectorized) ----------------
__global__ void k_update() {
    int i = blockIdx.x * 256 + threadIdx.x;    // grid 4096*256 = HWp*Cc/4
    int hw = i >> 6;                           // 64 float4 per row
    float cnt = d_cnt[hw];
    cnt = (cnt == 0.f) ? 1.f : cnt;
    float inv = 1.f / cnt;
    float4 a = ((const float4*)d_at)[i];
    float4 r = ((const float4*)d_rest)[i];
    a.x += r.x / cnt; a.y += r.y / cnt; a.z += r.z / cnt; a.w += r.w / cnt;
    (void)inv;
    ((float4*)d_at)[i] = a;
}

// ---------------- final: out[c][hw] = at[hw][c] + 2*rest2[hw][c]/cnt2[hw] ----------------
__global__ void k_writeout(float* __restrict__ out) {
    __shared__ float tile[32][33];
    int hw0 = blockIdx.x * 32;
    int c0  = blockIdx.y * 32;
    int tx = threadIdx.x;
    for (int i = threadIdx.y; i < 32; i += 8) {
        float cnt = d_cnt2[hw0 + i];
        cnt = (cnt == 0.f) ? 1.f : cnt;
        size_t idx = (size_t)(hw0 + i) * Cc + c0 + tx;
        tile[i][tx] = d_at[idx] + 2.f * d_rest2[idx] / cnt;
    }
    __syncthreads();
    for (int i = threadIdx.y; i < 32; i += 8)
        out[(size_t)(c0 + i) * HWp + hw0 + tx] = tile[tx][i];
}

// ---------------- host launcher (single stream) ----------------
extern "C" void kernel_launch(void* const* d_in, const int* in_sizes, int n_in,
                              void* d_out, int out_size) {
    const float* list_a = (const float*)d_in[0];
    const float* list_b = (const float*)d_in[1];
    const float* rots   = (const float*)d_in[3];
    const float* fxs    = (const float*)d_in[5];
    const float* cxs    = (const float*)d_in[6];
    const float* pos_a  = (const float*)d_in[7];
    const float* pos_b  = (const float*)d_in[8];
    const float* Wq     = (const float*)d_in[9];
    const float* bq     = (const float*)d_in[10];
    const float* Wk     = (const float*)d_in[11];
    const float* bk     = (const float*)d_in[12];
    const float* Wv     = (const float*)d_in[13];
    const float* bv     = (const float*)d_in[14];
    const float* in_w   = (const float*)d_in[15];
    const float* in_b   = (const float*)d_in[16];
    const float* out_w  = (const float*)d_in[17];
    const float* out_b  = (const float*)d_in[18];
    float* out = (float*)d_out;

    float *p_bc, *p_poskv, *p_rest, *p_rest2;
    __nv_bfloat16 *p_aseqbf, *p_btbf, *p_qqbf, *p_kkbf, *p_vvbf, *p_obf,
                  *p_WqT, *p_WkvT, *p_outwT;
    cudaGetSymbolAddress((void**)&p_bc,     d_bc);
    cudaGetSymbolAddress((void**)&p_poskv,  d_poskv);
    cudaGetSymbolAddress((void**)&p_rest,   d_rest);
    cudaGetSymbolAddress((void**)&p_rest2,  d_rest2);
    cudaGetSymbolAddress((void**)&p_aseqbf, d_aseqbf);
    cudaGetSymbolAddress((void**)&p_btbf,   d_btbf);
    cudaGetSymbolAddress((void**)&p_qqbf,   d_qqbf);
    cudaGetSymbolAddress((void**)&p_kkbf,   d_kkbf);
    cudaGetSymbolAddress((void**)&p_vvbf,   d_vvbf);
    cudaGetSymbolAddress((void**)&p_obf,    d_obf);
    cudaGetSymbolAddress((void**)&p_WqT,    d_WqT);
    cudaGetSymbolAddress((void**)&p_WkvT,   d_WkvT);
    cudaGetSymbolAddress((void**)&p_outwT,  d_outwT);

    cudaFuncSetAttribute(k_mma_gemm<1, 0>, cudaFuncAttributeMaxDynamicSharedMemorySize, GSM_TOTAL);
    cudaFuncSetAttribute(k_mma_gemm<1, 1>, cudaFuncAttributeMaxDynamicSharedMemorySize, GSM_TOTAL);
    cudaFuncSetAttribute(k_mma_gemm<2, 0>, cudaFuncAttributeMaxDynamicSharedMemorySize, GSM_TOTAL);

    k_zero<<<4096, 256>>>();                                                         // 0
    k_coords_all<<<dim3((NPTS + 255) / 256, 2), 256>>>(rots, fxs, cxs);              // 1
    k_combine_all<<<dim3(Cc, 4), Cc>>>(Wq, Wk, Wv, in_w, bq, bk, bv, in_b, out_w);   // 2
    k_pos_proj<<<dim3(H2c, 2), Cc>>>(pos_b);                                         // 3
    k_b2bt<<<dim3(MK / 32, Cc / 32), dim3(32, 8)>>>(list_b);                         // 4
    k_mma_gemm<1, 1><<<dim3(MK / 128, 4), 256, GSM_TOTAL>>>(                         // 5 <- profiled
        p_btbf, p_WkvT, p_poskv, p_kkbf, p_vvbf, nullptr, 512, 512, 0);
    k_transpose_in<<<dim3(HWp / 32, Cc / 32), dim3(32, 8)>>>(list_a);                // 6

    for (int ji = 0; ji < 2; ji++) {
        if (ji == 1) {
            k_b2bt<<<dim3(MK / 32, Cc / 32), dim3(32, 8)>>>(list_b + (size_t)3 * Cc * MK);
            k_mma_gemm<1, 1><<<dim3(MK / 128, 4), 256, GSM_TOTAL>>>(
                p_btbf, p_WkvT, p_poskv, p_kkbf, p_vvbf, nullptr, 512, 512, 0);
        }
        k_build_aseq<<<NPTS / 4, 256>>>(pos_a, ji);
        k_mma_gemm<1, 0><<<dim3(MQ / 128, 2), 256, GSM_TOTAL>>>(
            p_aseqbf, p_WqT, p_bc, p_qqbf, p_qqbf, nullptr, 256, 0, 0);
        k_attn_tc<<<dim3(W2c, 8), 128>>>();
        k_mma_gemm<2, 0><<<dim3(MQ / 128, 2), 256, GSM_TOTAL>>>(
            p_obf, p_outwT, out_b, nullptr, nullptr, ji == 0 ? p_rest : p_rest2,
            256, 0, ji * NPTS);
        if (ji == 0) k_update<<<4096, 256>>>();
    }
    k_writeout<<<dim3(HWp / 32, Cc / 32), dim3(32, 8)>>>(out);
}